// round 1
// baseline (speedup 1.0000x reference)
#include <cuda_runtime.h>
#include <math.h>

// ---------------------------------------------------------------------------
// YoloLoss: predictions (N,7,7,90) f32, target (N,7,7,85) f32 -> 4 scalars
// Layout per cell:
//   preds:  [0..79]=classes, [80]=obj2, [81..84]=box2, [85]=obj1, [86..89]=box1
//   target: [0..79]=classes, [80]=obj,  [81..84]=box
// Losses (reference semantics, incl. center loss = cx only):
//   coords = 5*( (pb.cx - t.cx)^2 + (sgnsqrt(pb.w)-sqrt(t.w))^2 + (sgnsqrt(pb.h)-sqrt(t.h))^2 )
//   obj    = (obj*op - obj)^2
//   noobj  = 0.5*((1-obj)*op - obj)^2
//   cls    = sum_c (p_c*obj - t_c)^2
// where chosen box/op picked by elementwise IoU argmax (idx = iou2 > iou1).
// ---------------------------------------------------------------------------

#define PRED_C 90
#define TGT_C  85

static constexpr int NBLOCKS  = 1024;
static constexpr int NTHREADS = 256;
static constexpr int NWARPS_PER_BLOCK = NTHREADS / 32;

__device__ float g_partials[NBLOCKS * 4];

__device__ __forceinline__ float iou_cxcywh(float ax, float ay, float aw, float ah,
                                            float bx, float by, float bw, float bh) {
    float ax1 = ax - aw * 0.5f, ay1 = ay - ah * 0.5f;
    float ax2 = ax + aw * 0.5f, ay2 = ay + ah * 0.5f;
    float bx1 = bx - bw * 0.5f, by1 = by - bh * 0.5f;
    float bx2 = bx + bw * 0.5f, by2 = by + bh * 0.5f;
    float iw = fminf(ax2, bx2) - fmaxf(ax1, bx1);
    float ih = fminf(ay2, by2) - fmaxf(ay1, by1);
    iw = fmaxf(iw, 0.0f);
    ih = fmaxf(ih, 0.0f);
    float inter  = iw * ih;
    float area_a = (ax2 - ax1) * (ay2 - ay1);
    float area_b = (bx2 - bx1) * (by2 - by1);
    return inter / (area_a + area_b - inter);
}

__device__ __forceinline__ float sgnsqrt(float x) {
    float s = (x > 0.0f) ? 1.0f : ((x < 0.0f) ? -1.0f : 0.0f);
    return s * sqrtf(fabsf(x) + 1e-6f);
}

__global__ __launch_bounds__(NTHREADS)
void yolo_loss_main(const float* __restrict__ P, const float* __restrict__ T,
                    int ncells) {
    const unsigned FULL = 0xffffffffu;
    int lane = threadIdx.x & 31;
    int warp_global = (blockIdx.x * NTHREADS + threadIdx.x) >> 5;
    int nwarps = (NBLOCKS * NTHREADS) >> 5;

    float acc_coord = 0.0f, acc_obj = 0.0f, acc_noobj = 0.0f, acc_cls = 0.0f;

    for (int cell = warp_global; cell < ncells; cell += nwarps) {
        const float* p = P + (size_t)cell * PRED_C;
        const float* t = T + (size_t)cell * TGT_C;

        // Coalesced cooperative loads: 3 chunks of 32 lanes each.
        float p0 = p[lane];
        float p1 = p[32 + lane];
        float p2 = (64 + lane < PRED_C) ? p[64 + lane] : 0.0f;  // lanes 0..25
        float t0 = t[lane];
        float t1 = t[32 + lane];
        float t2 = (64 + lane < TGT_C) ? t[64 + lane] : 0.0f;   // lanes 0..20

        // obj = target[80] -> chunk2 lane 16
        float obj = __shfl_sync(FULL, t2, 16);

        // Class loss: preds[0..79] vs target[0..79]
        {
            float d0 = p0 * obj - t0;  acc_cls += d0 * d0;     // j = 0..31
            float d1 = p1 * obj - t1;  acc_cls += d1 * d1;     // j = 32..63
            if (lane < 16) {                                    // j = 64..79
                float d2 = p2 * obj - t2;  acc_cls += d2 * d2;
            }
        }

        // Gather box scalars (all in chunk 2)
        float p80 = __shfl_sync(FULL, p2, 16);  // obj_pred for box2
        float b2x = __shfl_sync(FULL, p2, 17);
        float b2y = __shfl_sync(FULL, p2, 18);
        float b2w = __shfl_sync(FULL, p2, 19);
        float b2h = __shfl_sync(FULL, p2, 20);
        float p85 = __shfl_sync(FULL, p2, 21);  // obj_pred for box1
        float b1x = __shfl_sync(FULL, p2, 22);
        float b1y = __shfl_sync(FULL, p2, 23);
        float b1w = __shfl_sync(FULL, p2, 24);
        float b1h = __shfl_sync(FULL, p2, 25);
        float tbx = __shfl_sync(FULL, t2, 17);
        float tby = __shfl_sync(FULL, t2, 18);
        float tbw = __shfl_sync(FULL, t2, 19);
        float tbh = __shfl_sync(FULL, t2, 20);

        if (lane == 0) {
            float iou1 = iou_cxcywh(b1x, b1y, b1w, b1h, tbx, tby, tbw, tbh);
            float iou2 = iou_cxcywh(b2x, b2y, b2w, b2h, tbx, tby, tbw, tbh);
            bool pick2 = iou2 > iou1;  // numpy argmax: first max wins ties

            float bx = pick2 ? b2x : b1x;
            float bw = pick2 ? b2w : b1w;
            float bh = pick2 ? b2h : b1h;
            float op = pick2 ? p80 : p85;

            // pred_boxes = obj * chosen_box; center loss uses cx only ([..., :-3])
            float pbx = obj * bx;
            float pbw = obj * bw;
            float pbh = obj * bh;

            float dc = pbx - tbx;
            acc_coord += dc * dc;
            float dw = sgnsqrt(pbw) - sqrtf(tbw);
            acc_coord += dw * dw;
            float dh = sgnsqrt(pbh) - sqrtf(tbh);
            acc_coord += dh * dh;

            float e1 = obj * op - obj;
            acc_obj += e1 * e1;
            float e2 = (1.0f - obj) * op - obj;
            acc_noobj += e2 * e2;
        }
    }

    // Warp reduce each accumulator
    #pragma unroll
    for (int off = 16; off > 0; off >>= 1) {
        acc_coord += __shfl_xor_sync(FULL, acc_coord, off);
        acc_obj   += __shfl_xor_sync(FULL, acc_obj,   off);
        acc_noobj += __shfl_xor_sync(FULL, acc_noobj, off);
        acc_cls   += __shfl_xor_sync(FULL, acc_cls,   off);
    }

    __shared__ float sh[4][NWARPS_PER_BLOCK];
    int warp_local = threadIdx.x >> 5;
    if (lane == 0) {
        sh[0][warp_local] = acc_coord;
        sh[1][warp_local] = acc_obj;
        sh[2][warp_local] = acc_noobj;
        sh[3][warp_local] = acc_cls;
    }
    __syncthreads();

    if (threadIdx.x == 0) {
        float s0 = 0, s1 = 0, s2 = 0, s3 = 0;
        #pragma unroll
        for (int w = 0; w < NWARPS_PER_BLOCK; w++) {
            s0 += sh[0][w];  s1 += sh[1][w];  s2 += sh[2][w];  s3 += sh[3][w];
        }
        g_partials[blockIdx.x * 4 + 0] = s0;
        g_partials[blockIdx.x * 4 + 1] = s1;
        g_partials[blockIdx.x * 4 + 2] = s2;
        g_partials[blockIdx.x * 4 + 3] = s3;
    }
}

__global__ __launch_bounds__(256)
void yolo_loss_final(float* __restrict__ out) {
    __shared__ double sh[4][8];
    const unsigned FULL = 0xffffffffu;
    int tid = threadIdx.x;
    int lane = tid & 31;
    int warp = tid >> 5;

    double v0 = 0, v1 = 0, v2 = 0, v3 = 0;
    for (int b = tid; b < NBLOCKS; b += 256) {
        v0 += (double)g_partials[b * 4 + 0];
        v1 += (double)g_partials[b * 4 + 1];
        v2 += (double)g_partials[b * 4 + 2];
        v3 += (double)g_partials[b * 4 + 3];
    }
    #pragma unroll
    for (int off = 16; off > 0; off >>= 1) {
        v0 += __shfl_xor_sync(FULL, v0, off);
        v1 += __shfl_xor_sync(FULL, v1, off);
        v2 += __shfl_xor_sync(FULL, v2, off);
        v3 += __shfl_xor_sync(FULL, v3, off);
    }
    if (lane == 0) { sh[0][warp] = v0; sh[1][warp] = v1; sh[2][warp] = v2; sh[3][warp] = v3; }
    __syncthreads();
    if (tid == 0) {
        double c = 0, o = 0, n = 0, cl = 0;
        #pragma unroll
        for (int w = 0; w < 8; w++) {
            c += sh[0][w]; o += sh[1][w]; n += sh[2][w]; cl += sh[3][w];
        }
        out[0] = (float)(c * 5.0);   // coords_loss (LAMBDA_COORDS applied to both terms)
        out[1] = (float)o;           // obj_loss
        out[2] = (float)(n * 0.5);   // noobj_loss (LAMBDA_NOOBJ)
        out[3] = (float)cl;          // classes_loss
    }
}

extern "C" void kernel_launch(void* const* d_in, const int* in_sizes, int n_in,
                              void* d_out, int out_size) {
    const float* P = (const float*)d_in[0];   // predictions
    const float* T = (const float*)d_in[1];   // target
    float* out = (float*)d_out;

    int ncells = in_sizes[0] / PRED_C;        // 8192*7*7 = 401408

    yolo_loss_main<<<NBLOCKS, NTHREADS>>>(P, T, ncells);
    yolo_loss_final<<<1, 256>>>(out);
}

// round 2
// speedup vs baseline: 1.3409x; 1.3409x over previous
#include <cuda_runtime.h>
#include <math.h>

// ---------------------------------------------------------------------------
// YoloLoss: predictions (N,7,7,90) f32, target (N,7,7,85) f32 -> 4 scalars
// Per-cell layout:
//   preds:  [0..79]=classes, [80]=obj2, [81..84]=box2, [85]=obj1, [86..89]=box1
//   target: [0..79]=classes, [80]=obj,  [81..84]=box
// Strategy: smem-tile staging (coalesced float4), thread-per-cell scalar math,
// thread-parallel class loss, single kernel with last-block-done reduction.
// ---------------------------------------------------------------------------

#define PRED_C 90
#define TGT_C  85

static constexpr int CELLS   = 64;    // cells per tile
static constexpr int THREADS = 256;   // 8 warps
static constexpr int NBLOCKS = 608;   // 4 per SM (152 SMs), smem-limited to 5

__device__ float    g_partials[NBLOCKS * 4];
__device__ unsigned g_count = 0;

__device__ __forceinline__ float iou_cxcywh(float ax, float ay, float aw, float ah,
                                            float bx, float by, float bw, float bh) {
    float ax1 = ax - aw * 0.5f, ay1 = ay - ah * 0.5f;
    float ax2 = ax + aw * 0.5f, ay2 = ay + ah * 0.5f;
    float bx1 = bx - bw * 0.5f, by1 = by - bh * 0.5f;
    float bx2 = bx + bw * 0.5f, by2 = by + bh * 0.5f;
    float iw = fmaxf(fminf(ax2, bx2) - fmaxf(ax1, bx1), 0.0f);
    float ih = fmaxf(fminf(ay2, by2) - fmaxf(ay1, by1), 0.0f);
    float inter  = iw * ih;
    float area_a = (ax2 - ax1) * (ay2 - ay1);
    float area_b = (bx2 - bx1) * (by2 - by1);
    return inter / (area_a + area_b - inter);
}

__device__ __forceinline__ float sgnsqrt(float x) {
    float s = (x > 0.0f) ? 1.0f : ((x < 0.0f) ? -1.0f : 0.0f);
    return s * sqrtf(fabsf(x) + 1e-6f);
}

__global__ __launch_bounds__(THREADS)
void yolo_loss_fused(const float* __restrict__ P, const float* __restrict__ T,
                     float* __restrict__ out, int ncells) {
    __shared__ __align__(16) float sp[CELLS * PRED_C];  // 23040 B
    __shared__ __align__(16) float st[CELLS * TGT_C];   // 21760 B
    __shared__ float  red[4][THREADS / 32];
    __shared__ double dred[4][THREADS / 32];
    __shared__ int    s_last;

    const unsigned FULL = 0xffffffffu;
    const int tid  = threadIdx.x;
    const int lane = tid & 31;
    const int wrp  = tid >> 5;

    float aC = 0.0f, aO = 0.0f, aN = 0.0f, aL = 0.0f;

    const int ntiles = (ncells + CELLS - 1) / CELLS;
    for (int tile = blockIdx.x; tile < ntiles; tile += gridDim.x) {
        const int cbase = tile * CELLS;
        const int cells = min(CELLS, ncells - cbase);

        // ---- Stage tile to smem (coalesced) ----
        if (cells == CELLS) {
            const float4* gp  = reinterpret_cast<const float4*>(P + (size_t)cbase * PRED_C);
            float4*       spv = reinterpret_cast<float4*>(sp);
            for (int i = tid; i < CELLS * PRED_C / 4; i += THREADS) spv[i] = gp[i];
            const float4* gt  = reinterpret_cast<const float4*>(T + (size_t)cbase * TGT_C);
            float4*       stv = reinterpret_cast<float4*>(st);
            for (int i = tid; i < CELLS * TGT_C / 4; i += THREADS) stv[i] = gt[i];
        } else {
            for (int i = tid; i < cells * PRED_C; i += THREADS)
                sp[i] = P[(size_t)cbase * PRED_C + i];
            for (int i = tid; i < cells * TGT_C; i += THREADS)
                st[i] = T[(size_t)cbase * TGT_C + i];
        }
        __syncthreads();

        // ---- Class loss: thread-parallel over cells*80 elements ----
        const int nclass = cells * 80;
        for (int e = tid; e < nclass; e += THREADS) {
            unsigned c = (unsigned)e / 80u;
            unsigned k = (unsigned)e - c * 80u;
            float obj = st[c * TGT_C + 80];
            float d   = fmaf(sp[c * PRED_C + k], obj, -st[c * TGT_C + k]);
            aL = fmaf(d, d, aL);
        }

        // ---- Scalar per-cell math: one thread per cell ----
        if (tid < cells) {
            const float* pc = sp + tid * PRED_C;
            const float* tc = st + tid * TGT_C;
            float obj = tc[80];
            float tbx = tc[81], tby = tc[82], tbw = tc[83], tbh = tc[84];
            float p80 = pc[80];
            float b2x = pc[81], b2y = pc[82], b2w = pc[83], b2h = pc[84];
            float p85 = pc[85];
            float b1x = pc[86], b1y = pc[87], b1w = pc[88], b1h = pc[89];

            float iou1 = iou_cxcywh(b1x, b1y, b1w, b1h, tbx, tby, tbw, tbh);
            float iou2 = iou_cxcywh(b2x, b2y, b2w, b2h, tbx, tby, tbw, tbh);
            bool pick2 = iou2 > iou1;   // numpy argmax: first max wins ties

            float bx = pick2 ? b2x : b1x;
            float bw = pick2 ? b2w : b1w;
            float bh = pick2 ? b2h : b1h;
            float op = pick2 ? p80 : p85;

            // pred_boxes = obj * chosen box; center loss uses cx only ([..., :-3])
            float dc = fmaf(obj, bx, -tbx);
            aC = fmaf(dc, dc, aC);
            float dw = sgnsqrt(obj * bw) - sqrtf(tbw);
            aC = fmaf(dw, dw, aC);
            float dh = sgnsqrt(obj * bh) - sqrtf(tbh);
            aC = fmaf(dh, dh, aC);

            float e1 = fmaf(obj, op, -obj);
            aO = fmaf(e1, e1, aO);
            float e2 = fmaf(1.0f - obj, op, -obj);
            aN = fmaf(e2, e2, aN);
        }
        __syncthreads();  // before smem reuse next tile
    }

    // ---- Block reduction ----
    #pragma unroll
    for (int off = 16; off > 0; off >>= 1) {
        aC += __shfl_xor_sync(FULL, aC, off);
        aO += __shfl_xor_sync(FULL, aO, off);
        aN += __shfl_xor_sync(FULL, aN, off);
        aL += __shfl_xor_sync(FULL, aL, off);
    }
    if (lane == 0) {
        red[0][wrp] = aC; red[1][wrp] = aO; red[2][wrp] = aN; red[3][wrp] = aL;
    }
    __syncthreads();
    if (tid == 0) {
        float s0 = 0, s1 = 0, s2 = 0, s3 = 0;
        #pragma unroll
        for (int w = 0; w < THREADS / 32; w++) {
            s0 += red[0][w]; s1 += red[1][w]; s2 += red[2][w]; s3 += red[3][w];
        }
        g_partials[blockIdx.x * 4 + 0] = s0;
        g_partials[blockIdx.x * 4 + 1] = s1;
        g_partials[blockIdx.x * 4 + 2] = s2;
        g_partials[blockIdx.x * 4 + 3] = s3;
        __threadfence();
        unsigned prev = atomicAdd(&g_count, 1u);
        s_last = (prev == gridDim.x - 1) ? 1 : 0;
    }
    __syncthreads();

    // ---- Last block finalizes ----
    if (s_last) {
        double v0 = 0, v1 = 0, v2 = 0, v3 = 0;
        for (int b = tid; b < (int)gridDim.x; b += THREADS) {
            v0 += (double)__ldcg(&g_partials[b * 4 + 0]);
            v1 += (double)__ldcg(&g_partials[b * 4 + 1]);
            v2 += (double)__ldcg(&g_partials[b * 4 + 2]);
            v3 += (double)__ldcg(&g_partials[b * 4 + 3]);
        }
        #pragma unroll
        for (int off = 16; off > 0; off >>= 1) {
            v0 += __shfl_xor_sync(FULL, v0, off);
            v1 += __shfl_xor_sync(FULL, v1, off);
            v2 += __shfl_xor_sync(FULL, v2, off);
            v3 += __shfl_xor_sync(FULL, v3, off);
        }
        if (lane == 0) {
            dred[0][wrp] = v0; dred[1][wrp] = v1; dred[2][wrp] = v2; dred[3][wrp] = v3;
        }
        __syncthreads();
        if (tid == 0) {
            double c = 0, o = 0, n = 0, cl = 0;
            #pragma unroll
            for (int w = 0; w < THREADS / 32; w++) {
                c += dred[0][w]; o += dred[1][w]; n += dred[2][w]; cl += dred[3][w];
            }
            out[0] = (float)(c * 5.0);   // coords (LAMBDA_COORDS)
            out[1] = (float)o;           // obj
            out[2] = (float)(n * 0.5);   // noobj (LAMBDA_NOOBJ)
            out[3] = (float)cl;          // classes
            atomicExch(&g_count, 0u);    // reset for next graph replay
        }
    }
}

extern "C" void kernel_launch(void* const* d_in, const int* in_sizes, int n_in,
                              void* d_out, int out_size) {
    const float* P = (const float*)d_in[0];   // predictions
    const float* T = (const float*)d_in[1];   // target
    float* out = (float*)d_out;

    int ncells = in_sizes[0] / PRED_C;        // 8192*7*7 = 401408

    yolo_loss_fused<<<NBLOCKS, THREADS>>>(P, T, out, ncells);
}